// round 14
// baseline (speedup 1.0000x reference)
#include <cuda_runtime.h>
#include <math.h>

#define BB 2
#define SS 4096
#define DM 768
#define HH 12
#define OUTN 512
#define GRID 128
#define NTHR 512
#define XSTR 772             // x buffer row stride (floats)
#define XBUFF 12352          // 16*XSTR

// smem float offsets
#define OFF_U    0           // u_s [m][12h] : 9216 floats
#define OFF_X    9216        // 3 x-buffers (16 rows x 772) : 37056
#define OFF_E    46272       // e2 : 16 s x 8 ull = 256 floats
#define OFF_SCR  46528       // scr : 96 outs x 8 w8 ull = 1536 floats
#define SMEM_FLOATS 48064    // 192256 bytes

// ---------------- scratch ---------------------------------------------------
__device__ float g_qg[BB*DM];
__device__ float g_u[BB*DM*HH];          // [b][m][h]
__device__ float g_denom[BB*HH];
__device__ float g_y[GRID*HH*DM];        // per-block partial y [slot][h][m]
__device__ float g_og[BB*DM];            // init bvg, atomic accum
__device__ float g_part1[BB*DM];         // init bo,  atomic accum
__device__ float g_part2[BB*DM];         // init bp,  atomic accum
__device__ unsigned g_cnt;               // monotonic grid-barrier counter

typedef unsigned long long ull;

// ---------------- f32x2 helpers ---------------------------------------------
#define FMA2(d,a,b,c) asm("fma.rn.f32x2 %0, %1, %2, %3;" : "=l"(d) : "l"(a), "l"(b), "l"(c))
#define ADD2(d,a,b)   asm("add.rn.f32x2 %0, %1, %2;" : "=l"(d) : "l"(a), "l"(b))
#define PACK2(d,lo,hi) asm("mov.b64 %0, {%1,%2};" : "=l"(d) : "f"(lo), "f"(hi))
#define UNPK2(lo,hi,s) asm("mov.b64 {%0,%1}, %2;" : "=f"(lo), "=f"(hi) : "l"(s))

// ---------------- grid barrier (monotonic counter; replay-safe) -------------
__device__ __forceinline__ void gbar() {
    __syncthreads();
    if (threadIdx.x == 0) {
        __threadfence();
        unsigned arr = atomicAdd(&g_cnt, 1u);
        unsigned target = (arr / GRID + 1u) * GRID;
        while (*((volatile unsigned*)&g_cnt) < target) __nanosleep(32);
        __threadfence();
    }
    __syncthreads();
}

__global__ __launch_bounds__(NTHR, 1)
void k_mega(const float* __restrict__ x,   const float* __restrict__ wqg,
            const float* __restrict__ bqg, const float* __restrict__ wkg,
            const float* __restrict__ wvg, const float* __restrict__ bvg,
            const float* __restrict__ wo,  const float* __restrict__ bo,
            const float* __restrict__ wp,  const float* __restrict__ bp,
            const float* __restrict__ wfc, const float* __restrict__ bfc,
            float* __restrict__ out) {
    extern __shared__ __align__(16) float sm[];
    const int blk = blockIdx.x;
    const int t = threadIdx.x;

    // ======== Stage 0: accumulator inits + qg (blocks 0..23) ================
    {
        int j = blk*NTHR + t;
        if (j < 1536)       g_og[j]         = bvg[j % DM];
        else if (j < 3072)  g_part1[j-1536] = bo[(j-1536) % DM];
        else if (j < 4608)  g_part2[j-3072] = bp[(j-3072) % DM];
        else if (j < 5632)  out[j-4608]     = bfc[(j-4608) % OUTN];
        else if (j < 5656)  g_denom[j-5632] = 0.f;
    }
    if (blk < 24) {
        int b = blk / 12, h = blk % 12;
        float* x0s = sm; float* redA = sm + 768;
        for (int i = t; i < DM; i += NTHR) x0s[i] = x[(size_t)b*SS*DM + i];
        __syncthreads();
        int o = t & 63, part = t >> 6;                 // 8 parts of 96 m
        float acc = 0.f;
        const float* wc = wqg + h*64 + o;
        #pragma unroll 16
        for (int j = 0; j < 96; j++) {
            int m = part*96 + j;
            acc += x0s[m] * wc[(size_t)m*DM];
        }
        redA[t] = acc;
        __syncthreads();
        if (t < 64) {
            float s = bqg[h*64 + t];
            #pragma unroll
            for (int k = 0; k < 8; k++) s += redA[k*64 + t];
            g_qg[b*DM + h*64 + t] = s * 0.125f;
        }
    }
    gbar();

    // ======== Stage 1: u[b,m,h] = qg[b,h,:]·wkg[m,h*64:] ====================
    {
        int b = blk >> 6, mc = blk & 63;     // 12 m's per block
        float* qgs = sm;
        for (int i = t; i < DM; i += NTHR) qgs[i] = g_qg[b*DM + i];
        __syncthreads();
        if (t < 144) {
            int mi = t / 12, h = t % 12;
            int m = mc*12 + mi;
            const float* w = wkg + (size_t)m*DM + h*64;
            const float* q = qgs + h*64;
            float acc = 0.f;
            #pragma unroll
            for (int d = 0; d < 64; d++) acc += q[d] * w[d];
            g_u[((size_t)m + (size_t)b*DM)*HH + h] = acc;   // [b][m][h]
        }
    }
    gbar();

    // ======== Stage 2: broadcast-layout fused scores/exp/weighted-sums ======
    {
        const int b = blk >> 6;
        const int row0 = (blk & 63) * 64;
        float* u_s = sm + OFF_U;
        ull* e2  = (ull*)(sm + OFF_E);
        ull* scr = (ull*)(sm + OFF_SCR);

        // issue chunk st (16 rows) into buffer st%3; always commits a group
        auto issue = [&](int st) {
            if (st < 4 && t >= 192 && t < 448) {
                const float* gsrc = x + ((size_t)b*SS + row0 + st*16)*DM;
                float* buf = sm + OFF_X + (st % 3)*XBUFF;
                int q = t - 192;
                #pragma unroll
                for (int k = 0; k < 12; k++) {
                    int idx4 = q*12 + k;              // 0..3071
                    int row = idx4 / 192, c4 = idx4 % 192;
                    unsigned smaddr = (unsigned)__cvta_generic_to_shared(
                        buf + row*XSTR + c4*4);
                    const float4* g = (const float4*)(gsrc + (size_t)row*DM) + c4;
                    asm volatile("cp.async.cg.shared.global [%0], [%1], 16;"
                                 :: "r"(smaddr), "l"(g) : "memory");
                }
            }
            asm volatile("cp.async.commit_group;" ::: "memory");
        };

        issue(0);
        issue(1);

        // load u [m][12h] into smem (all threads, overlaps the copies)
        {
            const float4* src = (const float4*)(g_u + (size_t)b*DM*HH);
            float4* dst = (float4*)u_s;
            for (int i = t; i < DM*HH/4; i += NTHR) dst[i] = src[i];
        }

        // role ids
        const int isPh2 = (t < 192);
        const int f4g = t % 96, hh2 = t / 96;        // valid for t<192
        const int isPh1 = (t >= 192 && t < 448);
        const int q1 = t - 192;
        const int mg = q1 >> 2, rowg = q1 & 3;       // valid for ph1

        ull yacc[8][3];
        #pragma unroll
        for (int mi = 0; mi < 8; mi++)
            #pragma unroll
            for (int hp = 0; hp < 3; hp++) yacc[mi][hp] = 0ull;
        ull dull = 0ull;                             // t<96 denominator pairs

        for (int ci = 0; ci < 4; ci++) {
            asm volatile("cp.async.wait_group 1;" ::: "memory");
            __syncthreads();
            const float* xb = sm + OFF_X + (ci % 3)*XBUFF;

            // ---- phase 1: scores partials (256 threads)
            if (isPh1) {
                ull sc[4][6];
                #pragma unroll
                for (int r = 0; r < 4; r++)
                    #pragma unroll
                    for (int hp = 0; hp < 6; hp++) sc[r][hp] = 0ull;
                #pragma unroll
                for (int m4 = 0; m4 < 3; m4++) {
                    float4 xv0 = *(const float4*)(xb + (rowg*4+0)*XSTR + mg*12 + m4*4);
                    float4 xv1 = *(const float4*)(xb + (rowg*4+1)*XSTR + mg*12 + m4*4);
                    float4 xv2 = *(const float4*)(xb + (rowg*4+2)*XSTR + mg*12 + m4*4);
                    float4 xv3 = *(const float4*)(xb + (rowg*4+3)*XSTR + mg*12 + m4*4);
                    #pragma unroll
                    for (int mi = 0; mi < 4; mi++) {
                        int m = mg*12 + m4*4 + mi;
                        const ulonglong2* up = (const ulonglong2*)(u_s + m*12);
                        ulonglong2 u01 = up[0], u23 = up[1], u45 = up[2];
                        #pragma unroll
                        for (int r = 0; r < 4; r++) {
                            float xs = (r==0) ? ((mi==0)?xv0.x:(mi==1)?xv0.y:(mi==2)?xv0.z:xv0.w)
                                     : (r==1) ? ((mi==0)?xv1.x:(mi==1)?xv1.y:(mi==2)?xv1.z:xv1.w)
                                     : (r==2) ? ((mi==0)?xv2.x:(mi==1)?xv2.y:(mi==2)?xv2.z:xv2.w)
                                              : ((mi==0)?xv3.x:(mi==1)?xv3.y:(mi==2)?xv3.z:xv3.w);
                            ull xx; PACK2(xx, xs, xs);
                            FMA2(sc[r][0], xx, u01.x, sc[r][0]);
                            FMA2(sc[r][1], xx, u01.y, sc[r][1]);
                            FMA2(sc[r][2], xx, u23.x, sc[r][2]);
                            FMA2(sc[r][3], xx, u23.y, sc[r][3]);
                            FMA2(sc[r][4], xx, u45.x, sc[r][4]);
                            FMA2(sc[r][5], xx, u45.y, sc[r][5]);
                        }
                    }
                }
                // butterfly-reduce over the warp's 8 mg (lane bits [2:5))
                #pragma unroll
                for (int off = 4; off <= 16; off <<= 1)
                    #pragma unroll
                    for (int r = 0; r < 4; r++)
                        #pragma unroll
                        for (int hp = 0; hp < 6; hp++) {
                            ull o = __shfl_xor_sync(0xffffffffu, sc[r][hp], off);
                            ADD2(sc[r][hp], sc[r][hp], o);
                        }
                if ((q1 & 28) == 0) {                 // mg%8 == 0 lanes
                    int w8 = q1 >> 5;                 // warp's mg-octet 0..7
                    #pragma unroll
                    for (int r = 0; r < 4; r++)
                        #pragma unroll
                        for (int hp = 0; hp < 6; hp++)
                            scr[((rowg*4 + r)*6 + hp)*8 + w8] = sc[r][hp];
                }
            }
            __syncthreads();

            // ---- reduce over 8 octets + exp (t<96: out = r*6+hp)
            if (t < 96) {
                const ulonglong2* p = (const ulonglong2*)(scr + t*8);
                ulonglong2 pa = p[0], pb = p[1], pc = p[2], pd = p[3];
                ull s01, s23, s;
                ADD2(s01, pa.x, pa.y); ADD2(s23, pb.x, pb.y); ADD2(s01, s01, s23);
                ADD2(s23, pc.x, pc.y); ADD2(s, pd.x, pd.y);   ADD2(s23, s23, s);
                ADD2(s, s01, s23);
                float lo, hi; UNPK2(lo, hi, s);
                lo = __expf(lo); hi = __expf(hi);
                ull ev; PACK2(ev, lo, hi);
                int r = t / 6, hp = t % 6;
                e2[r*8 + (hp < 3 ? hp : hp + 1)] = ev;
                ADD2(dull, dull, ev);
            }
            __syncthreads();

            // ---- overlap: ph1 threads prefetch next chunk, ph2 computes
            issue(ci + 2);
            if (isPh2) {
                #pragma unroll 4
                for (int s = 0; s < 16; s++) {
                    float4 xa  = *(const float4*)(xb + s*XSTR + f4g*4);
                    float4 xbv = *(const float4*)(xb + s*XSTR + 384 + f4g*4);
                    const ulonglong2* ep = (const ulonglong2*)(e2 + s*8 + hh2*4);
                    ulonglong2 e01 = ep[0], e23 = ep[1];
                    ull ea = e01.x, eb = e01.y, ec = e23.x;
                    #pragma unroll
                    for (int mi = 0; mi < 4; mi++) {
                        float xs = (mi==0)?xa.x:(mi==1)?xa.y:(mi==2)?xa.z:xa.w;
                        ull xx; PACK2(xx, xs, xs);
                        FMA2(yacc[mi][0], ea, xx, yacc[mi][0]);
                        FMA2(yacc[mi][1], eb, xx, yacc[mi][1]);
                        FMA2(yacc[mi][2], ec, xx, yacc[mi][2]);
                    }
                    #pragma unroll
                    for (int mi = 0; mi < 4; mi++) {
                        float xs = (mi==0)?xbv.x:(mi==1)?xbv.y:(mi==2)?xbv.z:xbv.w;
                        ull xx; PACK2(xx, xs, xs);
                        FMA2(yacc[4+mi][0], ea, xx, yacc[4+mi][0]);
                        FMA2(yacc[4+mi][1], eb, xx, yacc[4+mi][1]);
                        FMA2(yacc[4+mi][2], ec, xx, yacc[4+mi][2]);
                    }
                }
            }
        }
        asm volatile("cp.async.wait_group 0;" ::: "memory");

        // ---- write this block's y slot [slot][h][m]
        if (isPh2) {
            #pragma unroll
            for (int mi = 0; mi < 8; mi++) {
                int m = (mi < 4) ? (f4g*4 + mi) : (384 + f4g*4 + (mi - 4));
                #pragma unroll
                for (int hp = 0; hp < 3; hp++) {
                    float lo, hi; UNPK2(lo, hi, yacc[mi][hp]);
                    int h = hh2*6 + hp*2;
                    g_y[((size_t)blk*HH + h    )*DM + m] = lo;
                    g_y[((size_t)blk*HH + h + 1)*DM + m] = hi;
                }
            }
        }
        __syncthreads();
        if (t < 96) scr[t] = dull;
        __syncthreads();
        if (t < 6) {
            ull s = 0ull;
            #pragma unroll
            for (int r = 0; r < 16; r++) ADD2(s, s, scr[r*6 + t]);
            float lo, hi; UNPK2(lo, hi, s);
            atomicAdd(&g_denom[b*HH + 2*t],     lo);
            atomicAdd(&g_denom[b*HH + 2*t + 1], hi);
        }
    }
    gbar();

    // ======== Stage 3: og = (y/denom) @ wvg slice (96 blocks) ===============
    if (blk < 96) {
        int b = blk / 48; int r = blk % 48;
        int h = r >> 2; int sub = r & 3;                 // 4 subs of 192 m
        float* redR = sm;            // 384
        float* y_s  = sm + 384;      // 192
        float* redG = sm + 768;      // 512
        float inv = 1.f / __ldcg(&g_denom[b*HH + h]);
        if (t < 384) {
            int e = t % 192, prt = t / 192;              // 2 parts x 32 slots
            float s = 0.f;
            #pragma unroll 8
            for (int sl = b*64 + prt*32; sl < b*64 + prt*32 + 32; sl++)
                s += g_y[((size_t)sl*HH + h)*DM + sub*192 + e];
            redR[t] = s;
        }
        __syncthreads();
        if (t < 192) y_s[t] = (redR[t] + redR[192+t]) * inv;
        __syncthreads();
        int o = t & 63, q = t >> 6;          // 8 parts of 24 m
        float acc = 0.f;
        const float* wc = wvg + h*64 + o;
        #pragma unroll
        for (int j = 0; j < 24; j++) {
            int ml = q*24 + j;
            acc += y_s[ml] * wc[(size_t)(sub*192 + ml)*DM];
        }
        redG[t] = acc;
        __syncthreads();
        if (t < 64) {
            float s = 0.f;
            #pragma unroll
            for (int k = 0; k < 8; k++) s += redG[k*64 + t];
            atomicAdd(&g_og[b*DM + h*64 + t], s);
        }
    }
    gbar();

    // ======== Stage 4: attn0 partials: og @ wo (72 blocks) ==================
    if (blk < 72) {
        int b = blk / 36; int r = blk % 36;
        int oc = r / 12;  int mcp = r % 12;      // 64-m chunk
        float* in_s = sm;
        if (t < 64) in_s[t] = __ldcg(&g_og[b*DM + mcp*64 + t]);
        __syncthreads();
        int o = oc*256 + (t & 255), mh = t >> 8;
        float acc = 0.f;
        const float* wc = wo + o;
        #pragma unroll
        for (int j = 0; j < 32; j++)
            acc += in_s[mh*32 + j] * wc[(size_t)(mcp*64 + mh*32 + j)*DM];
        atomicAdd(&g_part1[b*DM + o], acc);
    }
    gbar();

    // ======== Stage 5: pre-tanh pooled partials: attn0 @ wp =================
    if (blk < 72) {
        int b = blk / 36; int r = blk % 36;
        int oc = r / 12;  int mcp = r % 12;
        float* in_s = sm;
        __syncthreads();
        if (t < 64) in_s[t] = __ldcg(&g_part1[b*DM + mcp*64 + t]);
        __syncthreads();
        int o = oc*256 + (t & 255), mh = t >> 8;
        float acc = 0.f;
        const float* wc = wp + o;
        #pragma unroll
        for (int j = 0; j < 32; j++)
            acc += in_s[mh*32 + j] * wc[(size_t)(mcp*64 + mh*32 + j)*DM];
        atomicAdd(&g_part2[b*DM + o], acc);
    }
    gbar();

    // ======== Stage 6: out += tanh(part2) @ wfc (48 blocks) =================
    if (blk < 48) {
        int b = blk / 24; int r = blk % 24;
        int oc = r / 12;  int mcp = r % 12;
        float* in_s = sm;
        if (t < 64) in_s[t] = tanhf(__ldcg(&g_part2[b*DM + mcp*64 + t]));
        __syncthreads();
        int o = oc*256 + (t & 255), mh = t >> 8;
        float acc = 0.f;
        const float* wc = wfc + o;
        #pragma unroll
        for (int j = 0; j < 32; j++)
            acc += in_s[mh*32 + j] * wc[(size_t)(mcp*64 + mh*32 + j)*OUTN];
        atomicAdd(&out[b*OUTN + o], acc);
    }
}

// ---------------- launch ----------------------------------------------------
extern "C" void kernel_launch(void* const* d_in, const int* in_sizes, int n_in,
                              void* d_out, int out_size) {
    const float* x   = (const float*)d_in[0];
    const float* wqg = (const float*)d_in[7];
    const float* bqg = (const float*)d_in[8];
    const float* wkg = (const float*)d_in[9];
    const float* wvg = (const float*)d_in[11];
    const float* bvg = (const float*)d_in[12];
    const float* wo  = (const float*)d_in[13];
    const float* bo  = (const float*)d_in[14];
    const float* wp  = (const float*)d_in[15];
    const float* bp  = (const float*)d_in[16];
    const float* wfc = (const float*)d_in[17];
    const float* bfc = (const float*)d_in[18];
    float* out = (float*)d_out;

    const size_t smem = (size_t)SMEM_FLOATS * sizeof(float); // 192256 B
    static int configured = 0;
    if (!configured) {
        cudaFuncSetAttribute(k_mega, cudaFuncAttributeMaxDynamicSharedMemorySize,
                             (int)smem);
        configured = 1;
    }
    k_mega<<<GRID, NTHR, smem>>>(x, wqg, bqg, wkg, wvg, bvg, wo, bo, wp, bp,
                                 wfc, bfc, out);
}